// round 5
// baseline (speedup 1.0000x reference)
#include <cuda_runtime.h>

// ---------------------------------------------------------------------------
// Fused per-stage kernel: pointwise conv (into 3 smem windows) + dilated gated
// conv + 1x1 squeeze + residual + skip. 33 launches + 1 final head.
// fp32 with packed fma.rn.f32x2; weights pre-duplicated in smem so every
// FFMA2 operand is a direct LDS.64/LDS.128 (no pack/dup MOVs).
// ---------------------------------------------------------------------------

#define S3   3
#define BB   8
#define CH   16
#define GC   32
#define LL   4096
#define RR   24          // S3*BB rows
#define TILE 128
#define NTHR 256

typedef unsigned long long ull;

__device__ __forceinline__ ull dup2(float a) {
    ull r; asm("mov.b64 %0, {%1,%1};" : "=l"(r) : "f"(a)); return r;
}
__device__ __forceinline__ void upk(ull v, float &a, float &b) {
    asm("mov.b64 {%0,%1}, %2;" : "=f"(a), "=f"(b) : "l"(v));
}
__device__ __forceinline__ ull pk(float a, float b) {
    ull r; asm("mov.b64 %0, {%1,%2};" : "=l"(r) : "f"(a), "f"(b)); return r;
}
__device__ __forceinline__ ull f2fma(ull a, ull b, ull c) {
    ull r; asm("fma.rn.f32x2 %0, %1, %2, %3;" : "=l"(r) : "l"(a), "l"(b), "l"(c)); return r;
}
__device__ __forceinline__ float tanhap(float x) {
    float r; asm("tanh.approx.f32 %0, %1;" : "=f"(r) : "f"(x)); return r;
}
__device__ __forceinline__ float sigap(float x) {
    return fmaf(tanhap(x * 0.5f), 0.5f, 0.5f);
}

// Residual stream double buffer + skip accumulator, [row][c][l]
__device__ float g_XA[RR * CH * LL];
__device__ float g_XB[RR * CH * LL];
__device__ float g_SK[RR * CH * LL];

// Shared layout (float offsets). Duplicated (ull) regions marked D.
#define O_WFD 0          // 2048  (1024 weights, dup)
#define O_WGD 2048       // 2048
#define O_W2D 4096       // 1024  (512 weights, dup)
#define O_W1  5120       // 256
#define O_BFD 5376       // 64
#define O_BGD 5440       // 64
#define O_B2D 5504       // 32
#define O_B1  5536       // 16
#define O_H   5552       // 3 windows x 16 ch x 128 = 6144  (16B aligned)
#define O_Z   11696      // 32 ch x 128 = 4096              (16B aligned)
#define SM_FLOATS 15792  // 63168 bytes

// ---------------------------------------------------------------------------
template <bool FIRST>
__global__ void __launch_bounds__(NTHR, 3) k_stage(
        const float* __restrict__ Xsrc, float* __restrict__ Xdst,
        const float* __restrict__ xin,
        const float* __restrict__ pw, const float* __restrict__ pb,
        const float* __restrict__ cfw, const float* __restrict__ cfb,
        const float* __restrict__ cgw, const float* __restrict__ cgb,
        const float* __restrict__ c2w, const float* __restrict__ c2b,
        int i, int d, int last) {
    extern __shared__ float sm[];
    int tid = threadIdx.x;
    int row = blockIdx.y, s = row >> 3, bb = row & 7;
    int t0 = blockIdx.x * TILE;
    int a = d >> 1;

    // ---- stage weights -> smem (duplicated for packed FFMA2 operands) ----
    {
        int wb = s * 33 + i;
        const float* fsrc = cfw + wb * 1024;
        const float* gsrc = cgw + wb * 1024;
        ull* WFD = (ull*)(sm + O_WFD);
        ull* WGD = (ull*)(sm + O_WGD);
#pragma unroll
        for (int k = 0; k < 4; k++) {
            int idx = tid + k * 256;
            WFD[idx] = dup2(fsrc[idx]);
            WGD[idx] = dup2(gsrc[idx]);
        }
        const float* w2src = c2w + wb * 512;
        ull* W2D = (ull*)(sm + O_W2D);
        W2D[tid]       = dup2(w2src[tid]);
        W2D[tid + 256] = dup2(w2src[tid + 256]);
        if (FIRST) {
            if (tid < 16) { sm[O_W1 + tid] = pw[s * 16 + tid]; sm[O_B1 + tid] = pb[s * 16 + tid]; }
        } else {
            int pbase = (s * 32 + (i - 1));
            sm[O_W1 + tid] = pw[pbase * 256 + tid];
            if (tid < 16) sm[O_B1 + tid] = pb[pbase * 16 + tid];
        }
        if (tid < 32) {
            ((ull*)(sm + O_BFD))[tid] = dup2(cfb[wb * 32 + tid]);
            ((ull*)(sm + O_BGD))[tid] = dup2(cgb[wb * 32 + tid]);
        }
        if (tid < 16) ((ull*)(sm + O_B2D))[tid] = dup2(c2b[wb * 16 + tid]);
    }
    __syncthreads();

    // ---- fused pointwise: h = relu(W1 x + b1) into 3 smem windows ----
    // window 0: left taps  [t0-a, +128) | window 1: right taps [t0+d-a, +128)
    // window 2: center     [t0, +128)
    if (tid < 192) {
        int w = tid >> 6;
        int p = (tid & 63) * 2;
        int wstart = (w == 0) ? t0 - a : (w == 1) ? t0 + d - a : t0;
        int pos0 = wstart + p;
        bool in0 = (unsigned)pos0 < LL;
        bool in1 = (unsigned)(pos0 + 1) < LL;
        float* hdst = sm + O_H + w * 2048 + p;
        if (FIRST) {
            float x0 = in0 ? xin[(bb * LL + pos0) * 3 + s] : 0.f;
            float x1 = in1 ? xin[(bb * LL + pos0 + 1) * 3 + s] : 0.f;
            ull xa = pk(x0, x1);
#pragma unroll
            for (int o = 0; o < 16; o++) {
                ull r = f2fma(xa, dup2(sm[O_W1 + o]), dup2(sm[O_B1 + o]));
                float r0, r1; upk(r, r0, r1);
                hdst[o * 128]     = in0 ? fmaxf(r0, 0.f) : 0.f;
                hdst[o * 128 + 1] = in1 ? fmaxf(r1, 0.f) : 0.f;
            }
        } else {
            const float* Xr = Xsrc + row * CH * LL;
            // NOTE: pos0 can be odd (d=1 window starts at t0+1) -> scalar loads
            ull xa[16];
#pragma unroll
            for (int c = 0; c < 16; c++) {
                float x0 = in0 ? Xr[c * LL + pos0] : 0.f;
                float x1 = in1 ? Xr[c * LL + pos0 + 1] : 0.f;
                xa[c] = pk(x0, x1);
            }
#pragma unroll
            for (int o = 0; o < 16; o++) {
                ull acc = dup2(sm[O_B1 + o]);
#pragma unroll
                for (int c = 0; c < 16; c++)
                    acc = f2fma(xa[c], dup2(sm[O_W1 + o * 16 + c]), acc);
                float r0, r1; upk(acc, r0, r1);
                hdst[o * 128]     = in0 ? fmaxf(r0, 0.f) : 0.f;
                hdst[o * 128 + 1] = in1 ? fmaxf(r1, 0.f) : 0.f;
            }
        }
    }
    __syncthreads();

    // ---- main dilated gated conv: 4 oc x 4 consecutive positions / thread ----
    int q = tid >> 5, pg = tid & 31;
    int ocb = q * 4, p4 = pg * 4;

    const ull* WF = (const ull*)(sm + O_WFD);
    const ull* WG = (const ull*)(sm + O_WGD);

    ull fA[4][2], gA[4][2];
#pragma unroll
    for (int ii = 0; ii < 4; ii++) {
        ull fb = ((const ull*)(sm + O_BFD))[ocb + ii];
        ull gb = ((const ull*)(sm + O_BGD))[ocb + ii];
        fA[ii][0] = fb; fA[ii][1] = fb;
        gA[ii][0] = gb; gA[ii][1] = gb;
    }
#pragma unroll
    for (int c = 0; c < 16; c++) {
        ulonglong2 hl = *(const ulonglong2*)(sm + O_H + c * 128 + p4);
        ulonglong2 hr = *(const ulonglong2*)(sm + O_H + 2048 + c * 128 + p4);
#pragma unroll
        for (int ii = 0; ii < 4; ii++) {
            int wbase = ((ocb + ii) * 16 + c) * 2;
            ull wf0 = WF[wbase], wf1 = WF[wbase + 1];
            ull wg0 = WG[wbase], wg1 = WG[wbase + 1];
            fA[ii][0] = f2fma(hl.x, wf0, fA[ii][0]);
            fA[ii][0] = f2fma(hr.x, wf1, fA[ii][0]);
            fA[ii][1] = f2fma(hl.y, wf0, fA[ii][1]);
            fA[ii][1] = f2fma(hr.y, wf1, fA[ii][1]);
            gA[ii][0] = f2fma(hl.x, wg0, gA[ii][0]);
            gA[ii][0] = f2fma(hr.x, wg1, gA[ii][0]);
            gA[ii][1] = f2fma(hl.y, wg0, gA[ii][1]);
            gA[ii][1] = f2fma(hr.y, wg1, gA[ii][1]);
        }
    }
    // activations -> z smem
#pragma unroll
    for (int ii = 0; ii < 4; ii++) {
        float* zp = sm + O_Z + (ocb + ii) * 128 + p4;
        float f0, f1, f2, f3, g0, g1, g2, g3;
        upk(fA[ii][0], f0, f1); upk(fA[ii][1], f2, f3);
        upk(gA[ii][0], g0, g1); upk(gA[ii][1], g2, g3);
        float4 zv;
        zv.x = tanhap(f0) * sigap(g0);
        zv.y = tanhap(f1) * sigap(g1);
        zv.z = tanhap(f2) * sigap(g2);
        zv.w = tanhap(f3) * sigap(g3);
        *(float4*)zp = zv;
    }
    __syncthreads();

    // ---- z2 = relu(W2 z + b2); X = h + z2; SK += z2 ----
    int o0 = q * 2;
    const ull* W2 = (const ull*)(sm + O_W2D);
    ull acc[2][2];
#pragma unroll
    for (int oi = 0; oi < 2; oi++) {
        ull bv = ((const ull*)(sm + O_B2D))[o0 + oi];
        acc[oi][0] = bv; acc[oi][1] = bv;
    }
#pragma unroll 8
    for (int k = 0; k < 32; k++) {
        ulonglong2 zv = *(const ulonglong2*)(sm + O_Z + k * 128 + p4);
        ull w0 = W2[o0 * 32 + k];
        ull w1 = W2[(o0 + 1) * 32 + k];
        acc[0][0] = f2fma(zv.x, w0, acc[0][0]);
        acc[0][1] = f2fma(zv.y, w0, acc[0][1]);
        acc[1][0] = f2fma(zv.x, w1, acc[1][0]);
        acc[1][1] = f2fma(zv.y, w1, acc[1][1]);
    }
    float* SKg = g_SK + row * CH * LL;
#pragma unroll
    for (int oi = 0; oi < 2; oi++) {
        int o = o0 + oi;
        float4 hv = *(const float4*)(sm + O_H + 4096 + o * 128 + p4);
        float r0, r1, r2, r3;
        upk(acc[oi][0], r0, r1); upk(acc[oi][1], r2, r3);
        r0 = fmaxf(r0, 0.f); r1 = fmaxf(r1, 0.f);
        r2 = fmaxf(r2, 0.f); r3 = fmaxf(r3, 0.f);
        if (!last) {
            float4 xv = make_float4(hv.x + r0, hv.y + r1, hv.z + r2, hv.w + r3);
            *(float4*)(Xdst + (row * CH + o) * LL + t0 + p4) = xv;
        }
        float* so = SKg + o * LL + t0 + p4;
        if (FIRST) {
            *(float4*)so = make_float4(r0, r1, r2, r3);
        } else {
            float4 old = *(const float4*)so;
            *(float4*)so = make_float4(old.x + r0, old.y + r1, old.z + r2, old.w + r3);
        }
    }
}

// ---------------------------------------------------------------------------
// PinSage + final head (per position)
// ---------------------------------------------------------------------------
__global__ void __launch_bounds__(128) k_final(const float* __restrict__ n1w,
                                               const float* __restrict__ n1b,
                                               const float* __restrict__ n2w,
                                               const float* __restrict__ n2b,
                                               const float* __restrict__ upw,
                                               const float* __restrict__ upb,
                                               const float* __restrict__ fw,
                                               const float* __restrict__ fb,
                                               float* __restrict__ out) {
    __shared__ float s_n1w[768], s_n2w[768], s_n1b[48], s_n2b[48];
    __shared__ float s_upw[6144], s_upb[192], s_fw[64], s_fb;
    int tid = threadIdx.x;
    for (int idx = tid; idx < 768; idx += 128) { s_n1w[idx] = n1w[idx]; s_n2w[idx] = n2w[idx]; }
    for (int idx = tid; idx < 6144; idx += 128) s_upw[idx] = upw[idx];
    if (tid < 48) { s_n1b[tid] = n1b[tid]; s_n2b[tid] = n2b[tid]; }
    for (int idx = tid; idx < 192; idx += 128) s_upb[idx] = upb[idx];
    if (tid < 64) s_fw[tid] = fw[tid];
    if (tid == 0) s_fb = fb[0];
    __syncthreads();

    int gi = blockIdx.x * 128 + tid;
    int b = gi >> 12, l = gi & 4095;

    float F[3][16];
#pragma unroll
    for (int s = 0; s < 3; s++) {
        const float* sk = g_SK + (s * 8 + b) * CH * LL;
#pragma unroll
        for (int c = 0; c < 16; c++) F[s][c] = fmaxf(sk[c * LL + l], 0.f);
    }

    float m[64];
#pragma unroll
    for (int o = 0; o < 64; o++) m[o] = 0.f;

#pragma unroll
    for (int s = 0; s < 3; s++) {
        int n1 = (s == 0) ? 1 : 0;
        int n2 = (s == 2) ? 1 : 2;
        float nb[16];
#pragma unroll
        for (int o = 0; o < 16; o++) {
            float a1 = s_n1b[s * 16 + o], a2 = s_n2b[s * 16 + o];
#pragma unroll
            for (int c = 0; c < 16; c++) {
                a1 = fmaf(s_n1w[(s * 16 + o) * 16 + c], F[n1][c], a1);
                a2 = fmaf(s_n2w[(s * 16 + o) * 16 + c], F[n2][c], a2);
            }
            nb[o] = fmaxf(fmaxf(a1, 0.f), fmaxf(a2, 0.f));
        }
#pragma unroll 8
        for (int o = 0; o < 64; o++) {
            const float* wr = s_upw + (s * 64 + o) * 32;
            float u = s_upb[s * 64 + o];
#pragma unroll
            for (int c = 0; c < 16; c++) u = fmaf(wr[c], F[s][c], u);
#pragma unroll
            for (int c = 0; c < 16; c++) u = fmaf(wr[16 + c], nb[c], u);
            m[o] = fmaxf(m[o], fmaxf(u, 0.f));
        }
    }
    float logit = s_fb;
#pragma unroll
    for (int o = 0; o < 64; o++) logit = fmaf(s_fw[o], m[o], logit);
    out[gi] = fmaf(tanhap(logit * 0.5f), 0.5f, 0.5f);
}

// ---------------------------------------------------------------------------
extern "C" void kernel_launch(void* const* d_in, const int* in_sizes, int n_in,
                              void* d_out, int out_size) {
    const float* xin  = (const float*)d_in[0];
    const float* c1fw = (const float*)d_in[1];
    const float* c1fb = (const float*)d_in[2];
    const float* c1pw = (const float*)d_in[3];
    const float* c1pb = (const float*)d_in[4];
    const float* cfw  = (const float*)d_in[5];
    const float* cfb  = (const float*)d_in[6];
    const float* cgw  = (const float*)d_in[7];
    const float* cgb  = (const float*)d_in[8];
    const float* c2w  = (const float*)d_in[9];
    const float* c2b  = (const float*)d_in[10];
    const float* n1w  = (const float*)d_in[11];
    const float* n1b  = (const float*)d_in[12];
    const float* n2w  = (const float*)d_in[13];
    const float* n2b  = (const float*)d_in[14];
    const float* upw  = (const float*)d_in[15];
    const float* upb  = (const float*)d_in[16];
    const float* fw   = (const float*)d_in[17];
    const float* fb   = (const float*)d_in[18];
    float* out = (float*)d_out;

    const int smb = SM_FLOATS * 4;
    cudaFuncSetAttribute(k_stage<true>,  cudaFuncAttributeMaxDynamicSharedMemorySize, smb);
    cudaFuncSetAttribute(k_stage<false>, cudaFuncAttributeMaxDynamicSharedMemorySize, smb);

    float* xa; float* xb;
    cudaGetSymbolAddress((void**)&xa, g_XA);
    cudaGetSymbolAddress((void**)&xb, g_XB);
    float* bufs[2] = {xa, xb};

    dim3 gs(LL / TILE, RR), bs(NTHR);
    for (int i = 0; i < 33; i++) {
        int d = 1 << (i % 11);
        int last = (i == 32);
        float* dst = bufs[i & 1];
        const float* src = bufs[(i + 1) & 1];
        if (i == 0)
            k_stage<true><<<gs, bs, smb>>>(nullptr, dst, xin, c1fw, c1fb,
                                           cfw, cfb, cgw, cgb, c2w, c2b, i, d, last);
        else
            k_stage<false><<<gs, bs, smb>>>(src, dst, xin, c1pw, c1pb,
                                            cfw, cfb, cgw, cgb, c2w, c2b, i, d, last);
    }
    k_final<<<(BB * LL) / 128, 128>>>(n1w, n1b, n2w, n2b, upw, upb, fw, fb, out);
}